// round 15
// baseline (speedup 1.0000x reference)
#include <cuda_runtime.h>
#include <cuda_bf16.h>
#include <cuda_fp16.h>
#include <cstdint>
#include <math.h>

// Problem dims (fixed by the reference)
#define BB 64
#define TT 512
#define DD 2048
#define H1 256
#define H2 128
#define H3 64

#define NCTA_LSTM 72     // 2 groups x (16 L1 + 16 L2 + 4 L3)
#define NCTA_GEMM 2048   // 8 n-tiles x 256 m-tiles
#define TOTS (TT + 2)
#define RING 8

// ---------------- scratch (static device buffers; no allocation) ----------------
__device__ __align__(16) float g_xg1[(size_t)BB * TT * 4 * H1];   // 32768 x 1024
__device__ __align__(16) __nv_bfloat16 g_xbf[(size_t)BB * TT * DD];
__device__ __align__(16) __nv_bfloat16 g_W1bf[4 * H1 * DD];
__device__ __align__(16) float g_h3[BB * H3];         // layer-3 last h (fp32)
// per-group h ring buffers (fp16 mma A-fragment layout, u32 units), 8 deep
__device__ __align__(16) uint32_t g_b1[2][RING][4096];   // h1: 16 kb x 2 mt x 128 u32
__device__ __align__(16) uint32_t g_b2[2][RING][2048];   // h2:  8 kb
__device__ __align__(16) uint32_t g_b3[2][RING][1024];   // h3:  4 kb
__device__ unsigned g_flags[2][36 * 32];              // per-group per-CTA flags, 128B apart
__device__ unsigned g_xgcnt[4 * 32];                  // per-t-chunk gemm tile counters

// ---------------- helpers ----------------
__device__ __forceinline__ void mma_bf16(float* c, const uint32_t* a, const uint32_t* b) {
    asm volatile(
        "mma.sync.aligned.m16n8k16.row.col.f32.bf16.bf16.f32 "
        "{%0,%1,%2,%3}, {%4,%5,%6,%7}, {%8,%9}, {%0,%1,%2,%3};"
        : "+f"(c[0]), "+f"(c[1]), "+f"(c[2]), "+f"(c[3])
        : "r"(a[0]), "r"(a[1]), "r"(a[2]), "r"(a[3]), "r"(b[0]), "r"(b[1]));
}

__device__ __forceinline__ void mma_f16(float* c, const uint32_t* a, const uint32_t* b) {
    asm volatile(
        "mma.sync.aligned.m16n8k16.row.col.f32.f16.f16.f32 "
        "{%0,%1,%2,%3}, {%4,%5,%6,%7}, {%8,%9}, {%0,%1,%2,%3};"
        : "+f"(c[0]), "+f"(c[1]), "+f"(c[2]), "+f"(c[3])
        : "r"(a[0]), "r"(a[1]), "r"(a[2]), "r"(a[3]), "r"(b[0]), "r"(b[1]));
}

__device__ __forceinline__ void ldsm_x4(uint32_t* r, uint32_t addr) {
    asm volatile("ldmatrix.sync.aligned.m8n8.x4.shared.b16 {%0,%1,%2,%3}, [%4];"
                 : "=r"(r[0]), "=r"(r[1]), "=r"(r[2]), "=r"(r[3]) : "r"(addr));
}

__device__ __forceinline__ void cp_async16(uint32_t smem, const void* g) {
    asm volatile("cp.async.cg.shared.global [%0], [%1], 16;" :: "r"(smem), "l"(g));
}

__device__ __forceinline__ float4 ldcg4(const uint32_t* p) {
    float4 v;
    asm volatile("ld.global.cg.v4.f32 {%0,%1,%2,%3}, [%4];"
                 : "=f"(v.x), "=f"(v.y), "=f"(v.z), "=f"(v.w) : "l"(p));
    return v;
}

// single-MUFU activations (tanh.approx.f32, sm_75+)
__device__ __forceinline__ float tanh_a(float x) {
    float r;
    asm("tanh.approx.f32 %0, %1;" : "=f"(r) : "f"(x));
    return r;
}
__device__ __forceinline__ float fast_sig(float x) {
    return fmaf(0.5f, tanh_a(0.5f * x), 0.5f);
}
__device__ __forceinline__ float fast_tanh(float x) { return tanh_a(x); }

__device__ __forceinline__ uint32_t pack_h2(float a, float b) {
    __half2 h = __floats2half2_rn(a, b);
    return *reinterpret_cast<uint32_t*>(&h);
}

__device__ __forceinline__ unsigned ld_acq(const unsigned* p) {
    unsigned v;
    asm volatile("ld.acquire.gpu.global.u32 %0, [%1];" : "=r"(v) : "l"(p) : "memory");
    return v;
}

// ---------------- prep: zero flags/counters + h ring buffers (every replay) ----------
__global__ void prep_zero() {
    const int i = blockIdx.x * blockDim.x + threadIdx.x;
    if (i < 2 * 36 * 32) ((unsigned*)g_flags)[i] = 0u;
    if (i < 4 * 32) g_xgcnt[i] = 0u;
    const int n1 = 2 * RING * 4096, n2 = 2 * RING * 2048, n3 = 2 * RING * 1024;
    uint32_t* p1 = (uint32_t*)g_b1;
    uint32_t* p2 = (uint32_t*)g_b2;
    uint32_t* p3 = (uint32_t*)g_b3;
    const int stride = gridDim.x * blockDim.x;
    for (int k = i; k < n1; k += stride) p1[k] = 0u;
    for (int k = i; k < n2; k += stride) p2[k] = 0u;
    for (int k = i; k < n3; k += stride) p3[k] = 0u;
}

// ---------------- fp32 -> bf16 conversion (vectorized) ----------------
__global__ void f2bf_kernel(const float* __restrict__ src, __nv_bfloat16* __restrict__ dst, int n4) {
    const int stride = gridDim.x * blockDim.x;
    __nv_bfloat162* d2 = (__nv_bfloat162*)dst;
    for (int i = blockIdx.x * blockDim.x + threadIdx.x; i < n4; i += stride) {
        const float4 v = ((const float4*)src)[i];
        d2[2 * i]     = __floats2bfloat162_rn(v.x, v.y);
        d2[2 * i + 1] = __floats2bfloat162_rn(v.z, v.w);
    }
}

// ---------------- bf16 GEMM tile body (512 threads, 4-stage cp.async) ----------------
__device__ __forceinline__ void gemm_body(
    char* dyn, int gb,
    const __nv_bfloat16* __restrict__ A, const __nv_bfloat16* __restrict__ Bw,
    const float* __restrict__ b1, const float* __restrict__ b2,
    float* __restrict__ C, unsigned* __restrict__ xgcnt)
{
    constexpr int BM = 128, BN = 128, BK = 32;
    constexpr int LDA = BK + 8;
    constexpr int ST  = 4;
    constexpr int K   = DD;
    constexpr int N   = 4 * H1;
    __nv_bfloat16* As = (__nv_bfloat16*)dyn;
    __nv_bfloat16* Bs = As + ST * BM * LDA;

    const int tid  = threadIdx.x;
    const int lane = tid & 31;
    const int warp = tid >> 5;
    const int wm   = warp & 3;
    const int wn   = warp >> 2;

    const int nx    = gb & 7;
    const int myIdx = gb >> 3;           // 0..255
    const int tc    = myIdx >> 6;        // t-chunk 0..3
    const int bbat  = myIdx & 63;        // batch
    const long bm = (long)bbat * TT + (long)tc * 128;
    const long bn = (long)nx * BN;

    const uint32_t aBase = (uint32_t)__cvta_generic_to_shared(As);
    const uint32_t bBase = (uint32_t)__cvta_generic_to_shared(Bs);

    const int cr = tid >> 2;
    const int cs = (tid & 3) * 8;

    auto issue = [&](int st, int k0) {
        cp_async16(aBase + (uint32_t)(st * BM * LDA + cr * LDA + cs) * 2,
                   A + (size_t)(bm + cr) * K + k0 + cs);
        cp_async16(bBase + (uint32_t)(st * BN * LDA + cr * LDA + cs) * 2,
                   Bw + (size_t)(bn + cr) * K + k0 + cs);
    };

    const int KT = K / BK;

    issue(0, 0);
    asm volatile("cp.async.commit_group;");
    issue(1, BK);
    asm volatile("cp.async.commit_group;");
    issue(2, 2 * BK);
    asm volatile("cp.async.commit_group;");

    float acc[2][4][4];
#pragma unroll
    for (int mf = 0; mf < 2; ++mf)
#pragma unroll
        for (int nt = 0; nt < 4; ++nt)
#pragma unroll
            for (int q = 0; q < 4; ++q) acc[mf][nt][q] = 0.0f;

    const int aRow  = wm * 32 + (lane & 15);
    const int aColH = (lane >> 4) << 3;
    const int bRow  = wn * 32 + (((lane >> 4) & 1) << 3) + (lane & 7);
    const int bColH = ((lane >> 3) & 1) << 3;

    for (int kt = 0; kt < KT; ++kt) {
        asm volatile("cp.async.wait_group 2;");
        __syncthreads();
        if (kt + 3 < KT) issue((kt + 3) & (ST - 1), (kt + 3) * BK);
        asm volatile("cp.async.commit_group;");

        const int st = kt & (ST - 1);
        const uint32_t aS = aBase + (uint32_t)(st * BM * LDA) * 2;
        const uint32_t bS = bBase + (uint32_t)(st * BN * LDA) * 2;

#pragma unroll
        for (int kf = 0; kf < 2; ++kf) {
            const int k0 = kf * 16;
            uint32_t afr[2][4];
#pragma unroll
            for (int mf = 0; mf < 2; ++mf)
                ldsm_x4(afr[mf], aS + (uint32_t)((aRow + mf * 16) * LDA + k0 + aColH) * 2);
            uint32_t bfr[2][4];
#pragma unroll
            for (int np = 0; np < 2; ++np)
                ldsm_x4(bfr[np], bS + (uint32_t)((bRow + np * 16) * LDA + k0 + bColH) * 2);
#pragma unroll
            for (int mf = 0; mf < 2; ++mf)
#pragma unroll
                for (int nt = 0; nt < 4; ++nt)
                    mma_bf16(acc[mf][nt], afr[mf], &bfr[nt >> 1][(nt & 1) * 2]);
        }
    }

#pragma unroll
    for (int mf = 0; mf < 2; ++mf) {
#pragma unroll
        for (int nt = 0; nt < 4; ++nt) {
            const long r0 = bm + wm * 32 + mf * 16 + (lane >> 2);
            const long c0 = bn + wn * 32 + nt * 8 + 2 * (lane & 3);
            const float bias0 = b1[c0] + b2[c0];
            const float bias1 = b1[c0 + 1] + b2[c0 + 1];
            C[r0 * N + c0]           = acc[mf][nt][0] + bias0;
            C[r0 * N + c0 + 1]       = acc[mf][nt][1] + bias1;
            C[(r0 + 8) * N + c0]     = acc[mf][nt][2] + bias0;
            C[(r0 + 8) * N + c0 + 1] = acc[mf][nt][3] + bias1;
        }
    }

    __syncthreads();
    if (tid == 0) {
        asm volatile("red.release.gpu.global.add.u32 [%0], 1;"
                     :: "l"(xgcnt + tc * 32) : "memory");
    }
}

// ---------------- fused 3-layer LSTM role, 32-batch group, warp dataflow sync --------
// MT=2 m-tiles (32 batches). 16 warps = 2(mi) x KSN(ks) x NTG(ntg).
template <int ROLE, int H, int KP, int HC, int FIRST, bool LAST_ONLY>
__device__ __forceinline__ void lstm_role(
    char* dyn,
    const float* __restrict__ xg,
    const float* __restrict__ Wih,
    const float* __restrict__ Whh,
    const float* __restrict__ bih,
    const float* __restrict__ bhh,
    const uint32_t* __restrict__ ringP, int strideP,
    uint32_t* __restrict__ ringR, int strideR,
    float* __restrict__ hlast,
    unsigned* __restrict__ flags,
    unsigned* __restrict__ xgcnt,
    int ctaLocal, int myflag, int bofs)
{
    constexpr int MB   = 32;                  // batches per group
    constexpr int MT   = 2;                   // m-tiles
    constexpr int COLS = 4 * HC;
    constexpr int GSW  = COLS + 2;
    constexpr int NT   = COLS / 8;
    constexpr int NTG  = NT / 4;              // L1:2 L2:1 L3:2
    constexpr int KSN  = 16 / (MT * NTG);     // L1:4 L2:8 L3:4
    constexpr int KB_P = (KP > 0) ? KP / 16 : 0;
    constexpr int KBT  = KB_P + H / 16;
    constexpr int KS   = KBT / KSN;           // L1:4 L2:3 L3:3
    constexpr int ELEMS = MB * HC;            // L1:512 L2:256 L3:512
    static_assert(KS * KSN == KBT, "k split");
    static_assert(NTG * 4 == NT, "n split");

    float* gS = (float*)dyn;                  // KSN slabs * MB * GSW

    const int tid  = threadIdx.x;
    const int lane = tid & 31;
    const int w    = tid >> 5;
    const int grp  = lane >> 2;
    const int th4  = lane & 3;
    const int h0   = ctaLocal * HC;

    const int mi    = w & 1;
    const int wr    = w >> 1;                 // 0..7
    const int ks    = wr & (KSN - 1);
    const int ntg_i = wr / KSN;

    // ---- per-lane wait assignment ----
    int fIdx = -1, fOff = 0;
    if (ROLE == 1) {
        if (lane < KS)       { fIdx = ks * KS + lane; fOff = 0; }        // L1 producers
        else if (lane < KS + 16) { fIdx = 16 + (lane - KS); fOff = -6; } // L2 backpressure
    } else if (ROLE == 2) {
        if (lane < 2 * KS) {                 // 6 lanes
            const int q = lane >> 1, r = lane & 1;
            const int kb = ks * KS + q;
            fIdx = (kb < 16) ? kb : (16 + 2 * (kb - 16) + r);
            fOff = 0;
        } else if (lane < 2 * KS + 4) { fIdx = 32 + (lane - 2 * KS); fOff = -6; }
    } else {
        if (lane < 2 * KS) {                 // 6 lanes
            const int q = lane >> 1, r = lane & 1;
            const int kb = ks * KS + q;
            fIdx = (kb < 8) ? (16 + 2 * kb + r) : (32 + (kb - 8));
            fOff = 0;
        }
    }
    unsigned* const fPtr = (fIdx >= 0) ? (flags + fIdx * 32) : flags;

    // ---- weight B fragments in registers ----
    uint32_t bw[KS][4][2];
    {
        const int colb = lane >> 2;
        const int kk0  = (lane & 3) * 2;
#pragma unroll
        for (int q = 0; q < KS; ++q) {
            const int kbg = ks * KS + q;
#pragma unroll
            for (int nip = 0; nip < 4; ++nip) {
                const int c = (ntg_i * 4 + nip) * 8 + colb;
                const int g = c / HC, u = c % HC;
                const int row = g * H + h0 + u;
#pragma unroll
                for (int j = 0; j < 2; ++j) {
                    const int k = kbg * 16 + kk0 + j * 8;
                    float w0, w1;
                    if (KP > 0 && k < KP) {
                        const float* p = Wih + (size_t)row * KP + k;
                        w0 = p[0]; w1 = p[1];
                    } else {
                        const float* p = Whh + (size_t)row * H + (k - KP);
                        w0 = p[0]; w1 = p[1];
                    }
                    bw[q][nip][j] = pack_h2(w0, w1);
                }
            }
        }
    }

    // ---- elementwise ownership: thread -> (batch b, unit jj), 1 element ----
    const bool ew = (ELEMS == 512) || (tid < ELEMS);
    const int b  = tid / HC;                  // 0..31
    const int jj = tid % HC;

    float cst = 0.0f;
    float xr[4];
    float bias[4];
    if (ew && KP > 0) {
        const int kme = h0 + jj;
#pragma unroll
        for (int g = 0; g < 4; ++g) {
            const int r = g * H + kme;
            bias[g] = bih[r] + bhh[r];
        }
    }

    // ROLE1: wait for xg t-chunk 0, then initial prefetch of xg[t=0]
    if (KP == 0) {
        if (tid == 0) {
            while (ld_acq(xgcnt) < 512u) { }
        }
        __syncthreads();
        if (ew) {
            const float* xp = xg + ((size_t)(bofs + b) * TT) * (4 * H) + h0 + jj;
#pragma unroll
            for (int g = 0; g < 4; ++g) xr[g] = xp[(size_t)g * H];
        }
    }

    // ---- output fragment half-index ----
    const int mib   = b >> 4;                 // 0..1
    const int r_    = b & 15;
    const int lanew = (r_ & 7) * 4 + ((jj & 7) >> 1);
    const int comp  = (HC == 16) ? (((jj >> 3) & 1) * 2 + (r_ >> 3))
                                 : ((ctaLocal & 1) * 2 + (r_ >> 3));
    const int kbOwn = (HC == 16) ? ctaLocal : (ctaLocal >> 1);
    const int out_u32 = kbOwn * 256 + (mib * 32 + lanew) * 4 + comp;

    __syncthreads();

    for (int s = 0; s < TOTS; ++s) {
        const int t = s - FIRST;
        const bool active = (t >= 0) && (t < TT);

        if (active) {
            // ---- warp-granular dataflow wait ----
            {
                const int thr = s + fOff;
                bool ok = (fIdx < 0) || (thr <= 0);
                const unsigned utg = (unsigned)thr;
                while (!__all_sync(0xffffffffu, ok)) {
                    if (!ok) ok = (ld_acq(fPtr) >= utg);
                }
            }

            // ROLE1: at t-chunk boundaries ensure NEXT xg chunk ready (prefetch reads t+1)
            if (KP == 0) {
                const int tn = t + 1;
                if (tn < TT && (tn & 127) == 0) {
                    if (tid == 0) {
                        unsigned* cp = xgcnt + (tn >> 7) * 32;
                        while (ld_acq(cp) < 512u) { }
                    }
                    __syncthreads();
                }
            }

            // ---- mma: A fragments direct from ring (L2) ----
            const uint32_t* srcP = (KP > 0) ? (ringP + (size_t)(t & (RING - 1)) * strideP)
                                            : (const uint32_t*)0;
            const uint32_t* srcR = ringR + (size_t)((t - 1) & (RING - 1)) * strideR;

            float4 avv[KS];
#pragma unroll
            for (int q = 0; q < KS; ++q) {
                const int kb = ks * KS + q;
                const uint32_t* p = (KP > 0 && kb < KB_P)
                                        ? (srcP + ((size_t)(kb * MT + mi) * 32 + lane) * 4)
                                        : (srcR + ((size_t)((kb - KB_P) * MT + mi) * 32 + lane) * 4);
                avv[q] = ldcg4(p);
            }

            float acc[4][4];
#pragma unroll
            for (int nip = 0; nip < 4; ++nip)
#pragma unroll
                for (int q = 0; q < 4; ++q) acc[nip][q] = 0.0f;

#pragma unroll
            for (int q = 0; q < KS; ++q) {
                const uint32_t* au = (const uint32_t*)&avv[q];
#pragma unroll
                for (int nip = 0; nip < 4; ++nip)
                    mma_f16(acc[nip], au, bw[q][nip]);
            }

            float* gr = gS + ks * (MB * GSW) + (mi * 16 + grp) * GSW + 2 * th4;
#pragma unroll
            for (int nip = 0; nip < 4; ++nip) {
                const int cc = (ntg_i * 4 + nip) * 8;
                gr[cc]               = acc[nip][0];
                gr[cc + 1]           = acc[nip][1];
                gr[8 * GSW + cc]     = acc[nip][2];
                gr[8 * GSW + cc + 1] = acc[nip][3];
            }
        }
        __syncthreads();

        // ---- activation + direct STG of h into ring ----
        if (active && ew) {
            uint32_t* dstR = ringR + (size_t)(t & (RING - 1)) * strideR;
            float pi, pf, pg, po;
            if (KP == 0) { pi = xr[0]; pf = xr[1]; pg = xr[2]; po = xr[3]; }
            else         { pi = bias[0]; pf = bias[1]; pg = bias[2]; po = bias[3]; }
#pragma unroll
            for (int sl = 0; sl < KSN; ++sl) {
                const float* row = gS + sl * (MB * GSW) + b * GSW;
                pi += row[jj];
                pf += row[HC + jj];
                pg += row[2 * HC + jj];
                po += row[3 * HC + jj];
            }
            const float iv = fast_sig(pi), fv = fast_sig(pf);
            const float gv = fast_tanh(pg), ov = fast_sig(po);
            cst = fv * cst + iv * gv;
            const float h = ov * fast_tanh(cst);

            ((__half*)dstR)[out_u32 * 2 + (jj & 1)] = __float2half(h);

            if (LAST_ONLY && t == TT - 1)
                hlast[(size_t)(bofs + b) * H + h0 + jj] = h;

            if (KP == 0 && t + 1 < TT) {
                const float* xp = xg + ((size_t)(bofs + b) * TT + (t + 1)) * (4 * H) + h0 + jj;
#pragma unroll
                for (int g = 0; g < 4; ++g) xr[g] = xp[(size_t)g * H];
            }
        }
        __syncthreads();   // order STGs before release

        if (tid == 0) {
            asm volatile("st.release.gpu.global.u32 [%0], %1;"
                         :: "l"(flags + myflag * 32), "r"((unsigned)(s + 1)) : "memory");
        }
    }
}

// ---------------- mega kernel: 72 lstm CTAs + 2048 gemm CTAs ----------------
__global__ __launch_bounds__(512, 1) void mega(
    const __nv_bfloat16* __restrict__ xbf, const __nv_bfloat16* __restrict__ W1bf,
    const float* __restrict__ bih1, const float* __restrict__ bhh1,
    float* __restrict__ xg1,
    const float* __restrict__ Whh1,
    const float* __restrict__ Wih2, const float* __restrict__ Whh2,
    const float* __restrict__ bih2, const float* __restrict__ bhh2,
    const float* __restrict__ Wih3, const float* __restrict__ Whh3,
    const float* __restrict__ bih3, const float* __restrict__ bhh3,
    float* __restrict__ h3out, unsigned* __restrict__ xgcnt)
{
    extern __shared__ char dynls[];
    const int cb = blockIdx.x;
    if (cb < NCTA_LSTM) {
        const int gidx = cb / 36;         // group 0/1
        const int lc   = cb % 36;
        unsigned* fl   = (unsigned*)g_flags + gidx * (36 * 32);
        const int bofs = gidx * 32;
        if (lc < 16) {
            lstm_role<1, H1, 0, 16, 0, false>(dynls, xg1, nullptr, Whh1, nullptr, nullptr,
                                              nullptr, 0, &g_b1[gidx][0][0], 4096, nullptr,
                                              fl, xgcnt, lc, lc, bofs);
        } else if (lc < 32) {
            lstm_role<2, H2, H1, 8, 1, false>(dynls, nullptr, Wih2, Whh2, bih2, bhh2,
                                              &g_b1[gidx][0][0], 4096, &g_b2[gidx][0][0], 2048,
                                              nullptr, fl, xgcnt, lc - 16, lc, bofs);
        } else {
            lstm_role<3, H3, H2, 16, 2, true>(dynls, nullptr, Wih3, Whh3, bih3, bhh3,
                                              &g_b2[gidx][0][0], 2048, &g_b3[gidx][0][0], 1024,
                                              h3out, fl, xgcnt, lc - 32, lc, bofs);
        }
    } else {
        gemm_body(dynls, cb - NCTA_LSTM, xbf, W1bf, bih1, bhh1, xg1, xgcnt);
    }
}

// ---------------- head: deep/wide/concat/output (256 threads) ----------------
__global__ __launch_bounds__(256) void head_kernel(
    const float* __restrict__ x,
    const float* __restrict__ h3last,
    const float* __restrict__ Wd, const float* __restrict__ bd,
    const float* __restrict__ Ww, const float* __restrict__ bw,
    const float* __restrict__ Wo, const float* __restrict__ bo,
    float* __restrict__ out)
{
    const int bidx = blockIdx.x;
    const int j = threadIdx.x & 31;
    const int s = threadIdx.x >> 5;
    __shared__ float red[8][33];

    const float* xrow = x + ((size_t)bidx * TT + (TT - 1)) * DD;
    const float* wwr = Ww + (size_t)j * DD;
    float acc = 0.0f;
    const int k0 = s * (DD / 8);
#pragma unroll 4
    for (int k = k0; k < k0 + DD / 8; k += 4) {
        const float4 xv = *(const float4*)&xrow[k];
        const float4 wv = *(const float4*)&wwr[k];
        acc = fmaf(xv.x, wv.x, acc);
        acc = fmaf(xv.y, wv.y, acc);
        acc = fmaf(xv.z, wv.z, acc);
        acc = fmaf(xv.w, wv.w, acc);
    }
    red[s][j] = acc;
    __syncthreads();

    if (s == 0) {
        float wide = bw[j];
#pragma unroll
        for (int q = 0; q < 8; ++q) wide += red[q][j];
        wide = fmaxf(wide, 0.0f);

        const float* hrow = h3last + (size_t)bidx * H3;
        const float* wdr = Wd + (size_t)j * H3;
        float deep = bd[j];
#pragma unroll
        for (int k = 0; k < H3; ++k) deep = fmaf(hrow[k], wdr[k], deep);
        deep = fmaxf(deep, 0.0f);

        float v = deep * Wo[j] + wide * Wo[32 + j];
#pragma unroll
        for (int off = 16; off > 0; off >>= 1)
            v += __shfl_xor_sync(0xffffffffu, v, off);
        if (j == 0) out[bidx] = v + bo[0];
    }
}

// ---------------- launch ----------------
extern "C" void kernel_launch(void* const* d_in, const int* in_sizes, int n_in,
                              void* d_out, int out_size) {
    const float* x    = (const float*)d_in[0];
    const float* Wih1 = (const float*)d_in[1];
    const float* Whh1 = (const float*)d_in[2];
    const float* bih1 = (const float*)d_in[3];
    const float* bhh1 = (const float*)d_in[4];
    const float* Wih2 = (const float*)d_in[5];
    const float* Whh2 = (const float*)d_in[6];
    const float* bih2 = (const float*)d_in[7];
    const float* bhh2 = (const float*)d_in[8];
    const float* Wih3 = (const float*)d_in[9];
    const float* Whh3 = (const float*)d_in[10];
    const float* bih3 = (const float*)d_in[11];
    const float* bhh3 = (const float*)d_in[12];
    const float* Wd   = (const float*)d_in[13];
    const float* bd   = (const float*)d_in[14];
    const float* Ww   = (const float*)d_in[15];
    const float* bw   = (const float*)d_in[16];
    const float* Wo   = (const float*)d_in[17];
    const float* bo   = (const float*)d_in[18];
    float* out = (float*)d_out;

    float *xg1, *h3;
    __nv_bfloat16 *xbf, *W1bf;
    unsigned* xgcnt;
    cudaGetSymbolAddress((void**)&xg1,   g_xg1);
    cudaGetSymbolAddress((void**)&h3,    g_h3);
    cudaGetSymbolAddress((void**)&xbf,   g_xbf);
    cudaGetSymbolAddress((void**)&W1bf,  g_W1bf);
    cudaGetSymbolAddress((void**)&xgcnt, g_xgcnt);

    prep_zero<<<120, 512>>>();

    // convert x and Wih1 to bf16 for the big GEMM
    f2bf_kernel<<<4096, 256>>>(x,    xbf,  (BB * TT * DD) / 4);
    f2bf_kernel<<<512,  256>>>(Wih1, W1bf, (4 * H1 * DD) / 4);

    // mega kernel: gemm (producer, t-chunk-ordered) + 2 batch-group recurrences
    {
        const int dynBytes = 4 * (128 + 128) * 40 * 2;   // 81920 (gemm; lstm max ~34.8KB)
        cudaFuncSetAttribute(mega, cudaFuncAttributeMaxDynamicSharedMemorySize, dynBytes);
        mega<<<NCTA_LSTM + NCTA_GEMM, 512, dynBytes>>>(
            xbf, W1bf, bih1, bhh1, xg1,
            Whh1, Wih2, Whh2, bih2, bhh2,
            Wih3, Whh3, bih3, bhh3,
            h3, xgcnt);
    }

    // head
    head_kernel<<<BB, 256>>>(x, h3, Wd, bd, Ww, bw, Wo, bo, out);

    (void)in_sizes; (void)n_in; (void)out_size;
}

// round 16
// speedup vs baseline: 1.1537x; 1.1537x over previous
#include <cuda_runtime.h>
#include <cuda_bf16.h>
#include <cuda_fp16.h>
#include <cstdint>
#include <math.h>

// Problem dims (fixed by the reference)
#define BB 64
#define TT 512
#define DD 2048
#define H1 256
#define H2 128
#define H3 64

#define NCTA_LSTM 72     // 2 groups x (16 L1 + 16 L2 + 4 L3)
#define NCTA_GEMM 2048   // 8 n-tiles x 256 m-tiles
#define TOTS (TT + 2)
#define RING 8

// ---------------- scratch (static device buffers; no allocation) ----------------
__device__ __align__(16) float g_xg1[(size_t)BB * TT * 4 * H1];   // 32768 x 1024
__device__ __align__(16) __nv_bfloat16 g_xbf[(size_t)BB * TT * DD];
__device__ __align__(16) __nv_bfloat16 g_W1bf[4 * H1 * DD];
__device__ __align__(16) float g_h3[BB * H3];         // layer-3 last h (fp32)
// per-group h ring buffers (fp16 mma A-fragment layout, u32 units), 8 deep
__device__ __align__(16) uint32_t g_b1[2][RING][4096];   // h1: 16 kb x 2 mt x 128 u32
__device__ __align__(16) uint32_t g_b2[2][RING][2048];   // h2:  8 kb
__device__ __align__(16) uint32_t g_b3[2][RING][1024];   // h3:  4 kb
__device__ unsigned g_flags[2][36 * 32];              // per-group per-CTA flags, 128B apart
__device__ unsigned g_xgcnt[16 * 32];                 // (tc, group, n-parity) tile counters

// ---------------- helpers ----------------
__device__ __forceinline__ void mma_bf16(float* c, const uint32_t* a, const uint32_t* b) {
    asm volatile(
        "mma.sync.aligned.m16n8k16.row.col.f32.bf16.bf16.f32 "
        "{%0,%1,%2,%3}, {%4,%5,%6,%7}, {%8,%9}, {%0,%1,%2,%3};"
        : "+f"(c[0]), "+f"(c[1]), "+f"(c[2]), "+f"(c[3])
        : "r"(a[0]), "r"(a[1]), "r"(a[2]), "r"(a[3]), "r"(b[0]), "r"(b[1]));
}

__device__ __forceinline__ void mma_f16(float* c, const uint32_t* a, const uint32_t* b) {
    asm volatile(
        "mma.sync.aligned.m16n8k16.row.col.f32.f16.f16.f32 "
        "{%0,%1,%2,%3}, {%4,%5,%6,%7}, {%8,%9}, {%0,%1,%2,%3};"
        : "+f"(c[0]), "+f"(c[1]), "+f"(c[2]), "+f"(c[3])
        : "r"(a[0]), "r"(a[1]), "r"(a[2]), "r"(a[3]), "r"(b[0]), "r"(b[1]));
}

__device__ __forceinline__ void ldsm_x4(uint32_t* r, uint32_t addr) {
    asm volatile("ldmatrix.sync.aligned.m8n8.x4.shared.b16 {%0,%1,%2,%3}, [%4];"
                 : "=r"(r[0]), "=r"(r[1]), "=r"(r[2]), "=r"(r[3]) : "r"(addr));
}

__device__ __forceinline__ void cp_async16(uint32_t smem, const void* g) {
    asm volatile("cp.async.cg.shared.global [%0], [%1], 16;" :: "r"(smem), "l"(g));
}

__device__ __forceinline__ float4 ldcg4(const uint32_t* p) {
    float4 v;
    asm volatile("ld.global.cg.v4.f32 {%0,%1,%2,%3}, [%4];"
                 : "=f"(v.x), "=f"(v.y), "=f"(v.z), "=f"(v.w) : "l"(p));
    return v;
}

__device__ __forceinline__ float rcp_(float x) {
    float r;
    asm("rcp.approx.f32 %0, %1;" : "=f"(r) : "f"(x));
    return r;
}
__device__ __forceinline__ float fast_sig(float x) { return rcp_(1.0f + __expf(-x)); }
__device__ __forceinline__ float fast_tanh(float x) { return 2.0f * rcp_(1.0f + __expf(-2.0f * x)) - 1.0f; }

__device__ __forceinline__ uint32_t pack_h2(float a, float b) {
    __half2 h = __floats2half2_rn(a, b);
    return *reinterpret_cast<uint32_t*>(&h);
}

__device__ __forceinline__ unsigned ld_acq(const unsigned* p) {
    unsigned v;
    asm volatile("ld.acquire.gpu.global.u32 %0, [%1];" : "=r"(v) : "l"(p) : "memory");
    return v;
}

// ---------------- prep: zero flags/counters + h ring buffers (every replay) ----------
__global__ void prep_zero() {
    const int i = blockIdx.x * blockDim.x + threadIdx.x;
    if (i < 2 * 36 * 32) ((unsigned*)g_flags)[i] = 0u;
    if (i < 16 * 32) g_xgcnt[i] = 0u;
    const int n1 = 2 * RING * 4096, n2 = 2 * RING * 2048, n3 = 2 * RING * 1024;
    uint32_t* p1 = (uint32_t*)g_b1;
    uint32_t* p2 = (uint32_t*)g_b2;
    uint32_t* p3 = (uint32_t*)g_b3;
    const int stride = gridDim.x * blockDim.x;
    for (int k = i; k < n1; k += stride) p1[k] = 0u;
    for (int k = i; k < n2; k += stride) p2[k] = 0u;
    for (int k = i; k < n3; k += stride) p3[k] = 0u;
}

// ---------------- fp32 -> bf16 conversion (vectorized) ----------------
__global__ void f2bf_kernel(const float* __restrict__ src, __nv_bfloat16* __restrict__ dst, int n4) {
    const int stride = gridDim.x * blockDim.x;
    __nv_bfloat162* d2 = (__nv_bfloat162*)dst;
    for (int i = blockIdx.x * blockDim.x + threadIdx.x; i < n4; i += stride) {
        const float4 v = ((const float4*)src)[i];
        d2[2 * i]     = __floats2bfloat162_rn(v.x, v.y);
        d2[2 * i + 1] = __floats2bfloat162_rn(v.z, v.w);
    }
}

// ---------------- bf16 GEMM tile body (512 threads, 4-stage cp.async) ----------------
// One 128x128 tile of xg1; releases counter (tc, batch-group, n-parity) when done.
__device__ __forceinline__ void gemm_body(
    char* dyn, int gb,
    const __nv_bfloat16* __restrict__ A, const __nv_bfloat16* __restrict__ Bw,
    const float* __restrict__ b1, const float* __restrict__ b2,
    float* __restrict__ C, unsigned* __restrict__ xgcnt)
{
    constexpr int BM = 128, BN = 128, BK = 32;
    constexpr int LDA = BK + 8;
    constexpr int ST  = 4;
    constexpr int K   = DD;
    constexpr int N   = 4 * H1;
    __nv_bfloat16* As = (__nv_bfloat16*)dyn;
    __nv_bfloat16* Bs = As + ST * BM * LDA;

    const int tid  = threadIdx.x;
    const int lane = tid & 31;
    const int warp = tid >> 5;
    const int wm   = warp & 3;
    const int wn   = warp >> 2;

    const int nx    = gb & 7;
    const int myIdx = gb >> 3;           // 0..255
    const int tc    = myIdx >> 6;        // t-chunk 0..3
    const int bbat  = myIdx & 63;        // batch
    const long bm = (long)bbat * TT + (long)tc * 128;
    const long bn = (long)nx * BN;

    const uint32_t aBase = (uint32_t)__cvta_generic_to_shared(As);
    const uint32_t bBase = (uint32_t)__cvta_generic_to_shared(Bs);

    const int cr = tid >> 2;
    const int cs = (tid & 3) * 8;

    auto issue = [&](int st, int k0) {
        cp_async16(aBase + (uint32_t)(st * BM * LDA + cr * LDA + cs) * 2,
                   A + (size_t)(bm + cr) * K + k0 + cs);
        cp_async16(bBase + (uint32_t)(st * BN * LDA + cr * LDA + cs) * 2,
                   Bw + (size_t)(bn + cr) * K + k0 + cs);
    };

    const int KT = K / BK;

    issue(0, 0);
    asm volatile("cp.async.commit_group;");
    issue(1, BK);
    asm volatile("cp.async.commit_group;");
    issue(2, 2 * BK);
    asm volatile("cp.async.commit_group;");

    float acc[2][4][4];
#pragma unroll
    for (int mf = 0; mf < 2; ++mf)
#pragma unroll
        for (int nt = 0; nt < 4; ++nt)
#pragma unroll
            for (int q = 0; q < 4; ++q) acc[mf][nt][q] = 0.0f;

    const int aRow  = wm * 32 + (lane & 15);
    const int aColH = (lane >> 4) << 3;
    const int bRow  = wn * 32 + (((lane >> 4) & 1) << 3) + (lane & 7);
    const int bColH = ((lane >> 3) & 1) << 3;

    for (int kt = 0; kt < KT; ++kt) {
        asm volatile("cp.async.wait_group 2;");
        __syncthreads();
        if (kt + 3 < KT) issue((kt + 3) & (ST - 1), (kt + 3) * BK);
        asm volatile("cp.async.commit_group;");

        const int st = kt & (ST - 1);
        const uint32_t aS = aBase + (uint32_t)(st * BM * LDA) * 2;
        const uint32_t bS = bBase + (uint32_t)(st * BN * LDA) * 2;

#pragma unroll
        for (int kf = 0; kf < 2; ++kf) {
            const int k0 = kf * 16;
            uint32_t afr[2][4];
#pragma unroll
            for (int mf = 0; mf < 2; ++mf)
                ldsm_x4(afr[mf], aS + (uint32_t)((aRow + mf * 16) * LDA + k0 + aColH) * 2);
            uint32_t bfr[2][4];
#pragma unroll
            for (int np = 0; np < 2; ++np)
                ldsm_x4(bfr[np], bS + (uint32_t)((bRow + np * 16) * LDA + k0 + bColH) * 2);
#pragma unroll
            for (int mf = 0; mf < 2; ++mf)
#pragma unroll
                for (int nt = 0; nt < 4; ++nt)
                    mma_bf16(acc[mf][nt], afr[mf], &bfr[nt >> 1][(nt & 1) * 2]);
        }
    }

#pragma unroll
    for (int mf = 0; mf < 2; ++mf) {
#pragma unroll
        for (int nt = 0; nt < 4; ++nt) {
            const long r0 = bm + wm * 32 + mf * 16 + (lane >> 2);
            const long c0 = bn + wn * 32 + nt * 8 + 2 * (lane & 3);
            const float bias0 = b1[c0] + b2[c0];
            const float bias1 = b1[c0 + 1] + b2[c0 + 1];
            C[r0 * N + c0]           = acc[mf][nt][0] + bias0;
            C[r0 * N + c0 + 1]       = acc[mf][nt][1] + bias1;
            C[(r0 + 8) * N + c0]     = acc[mf][nt][2] + bias0;
            C[(r0 + 8) * N + c0 + 1] = acc[mf][nt][3] + bias1;
        }
    }

    __syncthreads();
    if (tid == 0) {
        const int cidx = tc * 4 + (bbat >> 5) * 2 + (nx & 1);
        asm volatile("red.release.gpu.global.add.u32 [%0], 1;"
                     :: "l"(xgcnt + cidx * 32) : "memory");
    }
}

// ---------------- fused 3-layer LSTM role, 32-batch group, warp dataflow sync --------
// MT=2 m-tiles (32 batches). 16 warps = 2(mi) x KSN(ks) x NTG(ntg).
// xgcnt is pre-offset by group (stride 4*32 per tc, 1*32 per n-parity).
template <int ROLE, int H, int KP, int HC, int FIRST, bool LAST_ONLY>
__device__ __forceinline__ void lstm_role(
    char* dyn,
    const float* __restrict__ xg,
    const float* __restrict__ Wih,
    const float* __restrict__ Whh,
    const float* __restrict__ bih,
    const float* __restrict__ bhh,
    const uint32_t* __restrict__ ringP, int strideP,
    uint32_t* __restrict__ ringR, int strideR,
    float* __restrict__ hlast,
    unsigned* __restrict__ flags,
    unsigned* __restrict__ xgcnt,
    int ctaLocal, int myflag, int bofs)
{
    constexpr int MB   = 32;                  // batches per group
    constexpr int MT   = 2;                   // m-tiles
    constexpr int COLS = 4 * HC;
    constexpr int GSW  = COLS + 2;
    constexpr int NT   = COLS / 8;
    constexpr int NTG  = NT / 4;              // L1:2 L2:1 L3:2
    constexpr int KSN  = 16 / (MT * NTG);     // L1:4 L2:8 L3:4
    constexpr int KB_P = (KP > 0) ? KP / 16 : 0;
    constexpr int KBT  = KB_P + H / 16;
    constexpr int KS   = KBT / KSN;           // L1:4 L2:3 L3:3
    constexpr int ELEMS = MB * HC;            // L1:512 L2:256 L3:512
    static_assert(KS * KSN == KBT, "k split");
    static_assert(NTG * 4 == NT, "n split");

    float* gS = (float*)dyn;                  // KSN slabs * MB * GSW

    const int tid  = threadIdx.x;
    const int lane = tid & 31;
    const int w    = tid >> 5;
    const int grp  = lane >> 2;
    const int th4  = lane & 3;
    const int h0   = ctaLocal * HC;
    const int nxp  = ctaLocal >> 3;           // n-parity of my xg columns (ROLE 1)

    const int mi    = w & 1;
    const int wr    = w >> 1;                 // 0..7
    const int ks    = wr & (KSN - 1);
    const int ntg_i = wr / KSN;

    // ---- per-lane wait assignment ----
    int fIdx = -1, fOff = 0;
    if (ROLE == 1) {
        if (lane < KS)       { fIdx = ks * KS + lane; fOff = 0; }        // L1 producers
        else if (lane < KS + 16) { fIdx = 16 + (lane - KS); fOff = -6; } // L2 backpressure
    } else if (ROLE == 2) {
        if (lane < 2 * KS) {                 // 6 lanes
            const int q = lane >> 1, r = lane & 1;
            const int kb = ks * KS + q;
            fIdx = (kb < 16) ? kb : (16 + 2 * (kb - 16) + r);
            fOff = 0;
        } else if (lane < 2 * KS + 4) { fIdx = 32 + (lane - 2 * KS); fOff = -6; }
    } else {
        if (lane < 2 * KS) {                 // 6 lanes
            const int q = lane >> 1, r = lane & 1;
            const int kb = ks * KS + q;
            fIdx = (kb < 8) ? (16 + 2 * kb + r) : (32 + (kb - 8));
            fOff = 0;
        }
    }
    unsigned* const fPtr = (fIdx >= 0) ? (flags + fIdx * 32) : flags;

    // ---- weight B fragments in registers ----
    uint32_t bw[KS][4][2];
    {
        const int colb = lane >> 2;
        const int kk0  = (lane & 3) * 2;
#pragma unroll
        for (int q = 0; q < KS; ++q) {
            const int kbg = ks * KS + q;
#pragma unroll
            for (int nip = 0; nip < 4; ++nip) {
                const int c = (ntg_i * 4 + nip) * 8 + colb;
                const int g = c / HC, u = c % HC;
                const int row = g * H + h0 + u;
#pragma unroll
                for (int j = 0; j < 2; ++j) {
                    const int k = kbg * 16 + kk0 + j * 8;
                    float w0, w1;
                    if (KP > 0 && k < KP) {
                        const float* p = Wih + (size_t)row * KP + k;
                        w0 = p[0]; w1 = p[1];
                    } else {
                        const float* p = Whh + (size_t)row * H + (k - KP);
                        w0 = p[0]; w1 = p[1];
                    }
                    bw[q][nip][j] = pack_h2(w0, w1);
                }
            }
        }
    }

    // ---- elementwise ownership: thread -> (batch b, unit jj), 1 element ----
    const bool ew = (ELEMS == 512) || (tid < ELEMS);
    const int b  = tid / HC;                  // 0..31
    const int jj = tid % HC;

    float cst = 0.0f;
    float xr[4];
    float bias[4];
    if (ew && KP > 0) {
        const int kme = h0 + jj;
#pragma unroll
        for (int g = 0; g < 4; ++g) {
            const int r = g * H + kme;
            bias[g] = bih[r] + bhh[r];
        }
    }

    // ROLE1: wait for my (group, n-parity) slice of xg t-chunk 0 (128 tiles)
    if (KP == 0) {
        if (tid == 0) {
            while (ld_acq(xgcnt + nxp * 32) < 128u) { }
        }
        __syncthreads();
        if (ew) {
            const float* xp = xg + ((size_t)(bofs + b) * TT) * (4 * H) + h0 + jj;
#pragma unroll
            for (int g = 0; g < 4; ++g) xr[g] = xp[(size_t)g * H];
        }
    }

    // ---- output fragment half-index ----
    const int mib   = b >> 4;                 // 0..1
    const int r_    = b & 15;
    const int lanew = (r_ & 7) * 4 + ((jj & 7) >> 1);
    const int comp  = (HC == 16) ? (((jj >> 3) & 1) * 2 + (r_ >> 3))
                                 : ((ctaLocal & 1) * 2 + (r_ >> 3));
    const int kbOwn = (HC == 16) ? ctaLocal : (ctaLocal >> 1);
    const int out_u32 = kbOwn * 256 + (mib * 32 + lanew) * 4 + comp;

    __syncthreads();

    for (int s = 0; s < TOTS; ++s) {
        const int t = s - FIRST;
        const bool active = (t >= 0) && (t < TT);

        if (active) {
            // ---- warp-granular dataflow wait ----
            {
                const int thr = s + fOff;
                bool ok = (fIdx < 0) || (thr <= 0);
                const unsigned utg = (unsigned)thr;
                while (!__all_sync(0xffffffffu, ok)) {
                    if (!ok) ok = (ld_acq(fPtr) >= utg);
                }
            }

            // ROLE1: at t-chunk boundaries ensure NEXT xg chunk slice ready
            if (KP == 0) {
                const int tn = t + 1;
                if (tn < TT && (tn & 127) == 0) {
                    if (tid == 0) {
                        unsigned* cp = xgcnt + ((tn >> 7) * 4 + nxp) * 32;
                        while (ld_acq(cp) < 128u) { }
                    }
                    __syncthreads();
                }
            }

            // ---- mma: A fragments direct from ring (L2) ----
            const uint32_t* srcP = (KP > 0) ? (ringP + (size_t)(t & (RING - 1)) * strideP)
                                            : (const uint32_t*)0;
            const uint32_t* srcR = ringR + (size_t)((t - 1) & (RING - 1)) * strideR;

            float4 avv[KS];
#pragma unroll
            for (int q = 0; q < KS; ++q) {
                const int kb = ks * KS + q;
                const uint32_t* p = (KP > 0 && kb < KB_P)
                                        ? (srcP + ((size_t)(kb * MT + mi) * 32 + lane) * 4)
                                        : (srcR + ((size_t)((kb - KB_P) * MT + mi) * 32 + lane) * 4);
                avv[q] = ldcg4(p);
            }

            float acc[4][4];
#pragma unroll
            for (int nip = 0; nip < 4; ++nip)
#pragma unroll
                for (int q = 0; q < 4; ++q) acc[nip][q] = 0.0f;

#pragma unroll
            for (int q = 0; q < KS; ++q) {
                const uint32_t* au = (const uint32_t*)&avv[q];
#pragma unroll
                for (int nip = 0; nip < 4; ++nip)
                    mma_f16(acc[nip], au, bw[q][nip]);
            }

            float* gr = gS + ks * (MB * GSW) + (mi * 16 + grp) * GSW + 2 * th4;
#pragma unroll
            for (int nip = 0; nip < 4; ++nip) {
                const int cc = (ntg_i * 4 + nip) * 8;
                gr[cc]               = acc[nip][0];
                gr[cc + 1]           = acc[nip][1];
                gr[8 * GSW + cc]     = acc[nip][2];
                gr[8 * GSW + cc + 1] = acc[nip][3];
            }
        }
        __syncthreads();

        // ---- activation + direct STG of h into ring ----
        if (active && ew) {
            uint32_t* dstR = ringR + (size_t)(t & (RING - 1)) * strideR;
            float pi, pf, pg, po;
            if (KP == 0) { pi = xr[0]; pf = xr[1]; pg = xr[2]; po = xr[3]; }
            else         { pi = bias[0]; pf = bias[1]; pg = bias[2]; po = bias[3]; }
#pragma unroll
            for (int sl = 0; sl < KSN; ++sl) {
                const float* row = gS + sl * (MB * GSW) + b * GSW;
                pi += row[jj];
                pf += row[HC + jj];
                pg += row[2 * HC + jj];
                po += row[3 * HC + jj];
            }
            const float iv = fast_sig(pi), fv = fast_sig(pf);
            const float gv = fast_tanh(pg), ov = fast_sig(po);
            cst = fv * cst + iv * gv;
            const float h = ov * fast_tanh(cst);

            ((__half*)dstR)[out_u32 * 2 + (jj & 1)] = __float2half(h);

            if (LAST_ONLY && t == TT - 1)
                hlast[(size_t)(bofs + b) * H + h0 + jj] = h;

            if (KP == 0 && t + 1 < TT) {
                const float* xp = xg + ((size_t)(bofs + b) * TT + (t + 1)) * (4 * H) + h0 + jj;
#pragma unroll
                for (int g = 0; g < 4; ++g) xr[g] = xp[(size_t)g * H];
            }
        }
        __syncthreads();   // order STGs before release

        if (tid == 0) {
            asm volatile("st.release.gpu.global.u32 [%0], %1;"
                         :: "l"(flags + myflag * 32), "r"((unsigned)(s + 1)) : "memory");
        }
    }
}

// ---------------- mega kernel: 72 lstm CTAs + 2048 gemm CTAs ----------------
__global__ __launch_bounds__(512, 1) void mega(
    const __nv_bfloat16* __restrict__ xbf, const __nv_bfloat16* __restrict__ W1bf,
    const float* __restrict__ bih1, const float* __restrict__ bhh1,
    float* __restrict__ xg1,
    const float* __restrict__ Whh1,
    const float* __restrict__ Wih2, const float* __restrict__ Whh2,
    const float* __restrict__ bih2, const float* __restrict__ bhh2,
    const float* __restrict__ Wih3, const float* __restrict__ Whh3,
    const float* __restrict__ bih3, const float* __restrict__ bhh3,
    float* __restrict__ h3out, unsigned* __restrict__ xgcnt)
{
    extern __shared__ char dynls[];
    const int cb = blockIdx.x;
    if (cb < NCTA_LSTM) {
        const int gidx = cb / 36;         // group 0/1
        const int lc   = cb % 36;
        unsigned* fl   = (unsigned*)g_flags + gidx * (36 * 32);
        unsigned* xc   = xgcnt + gidx * 64;   // group-offset counters
        const int bofs = gidx * 32;
        if (lc < 16) {
            lstm_role<1, H1, 0, 16, 0, false>(dynls, xg1, nullptr, Whh1, nullptr, nullptr,
                                              nullptr, 0, &g_b1[gidx][0][0], 4096, nullptr,
                                              fl, xc, lc, lc, bofs);
        } else if (lc < 32) {
            lstm_role<2, H2, H1, 8, 1, false>(dynls, nullptr, Wih2, Whh2, bih2, bhh2,
                                              &g_b1[gidx][0][0], 4096, &g_b2[gidx][0][0], 2048,
                                              nullptr, fl, xc, lc - 16, lc, bofs);
        } else {
            lstm_role<3, H3, H2, 16, 2, true>(dynls, nullptr, Wih3, Whh3, bih3, bhh3,
                                              &g_b2[gidx][0][0], 2048, &g_b3[gidx][0][0], 1024,
                                              h3out, fl, xc, lc - 32, lc, bofs);
        }
    } else {
        gemm_body(dynls, cb - NCTA_LSTM, xbf, W1bf, bih1, bhh1, xg1, xgcnt);
    }
}

// ---------------- head: deep/wide/concat/output (256 threads) ----------------
__global__ __launch_bounds__(256) void head_kernel(
    const float* __restrict__ x,
    const float* __restrict__ h3last,
    const float* __restrict__ Wd, const float* __restrict__ bd,
    const float* __restrict__ Ww, const float* __restrict__ bw,
    const float* __restrict__ Wo, const float* __restrict__ bo,
    float* __restrict__ out)
{
    const int bidx = blockIdx.x;
    const int j = threadIdx.x & 31;
    const int s = threadIdx.x >> 5;
    __shared__ float red[8][33];

    const float* xrow = x + ((size_t)bidx * TT + (TT - 1)) * DD;
    const float* wwr = Ww + (size_t)j * DD;
    float acc = 0.0f;
    const int k0 = s * (DD / 8);
#pragma unroll 4
    for (int k = k0; k < k0 + DD / 8; k += 4) {
        const float4 xv = *(const float4*)&xrow[k];
        const float4 wv = *(const float4*)&wwr[k];
        acc = fmaf(xv.x, wv.x, acc);
        acc = fmaf(xv.y, wv.y, acc);
        acc = fmaf(xv.z, wv.z, acc);
        acc = fmaf(xv.w, wv.w, acc);
    }
    red[s][j] = acc;
    __syncthreads();

    if (s == 0) {
        float wide = bw[j];
#pragma unroll
        for (int q = 0; q < 8; ++q) wide += red[q][j];
        wide = fmaxf(wide, 0.0f);

        const float* hrow = h3last + (size_t)bidx * H3;
        const float* wdr = Wd + (size_t)j * H3;
        float deep = bd[j];
#pragma unroll
        for (int k = 0; k < H3; ++k) deep = fmaf(hrow[k], wdr[k], deep);
        deep = fmaxf(deep, 0.0f);

        float v = deep * Wo[j] + wide * Wo[32 + j];
#pragma unroll
        for (int off = 16; off > 0; off >>= 1)
            v += __shfl_xor_sync(0xffffffffu, v, off);
        if (j == 0) out[bidx] = v + bo[0];
    }
}

// ---------------- launch ----------------
extern "C" void kernel_launch(void* const* d_in, const int* in_sizes, int n_in,
                              void* d_out, int out_size) {
    const float* x    = (const float*)d_in[0];
    const float* Wih1 = (const float*)d_in[1];
    const float* Whh1 = (const float*)d_in[2];
    const float* bih1 = (const float*)d_in[3];
    const float* bhh1 = (const float*)d_in[4];
    const float* Wih2 = (const float*)d_in[5];
    const float* Whh2 = (const float*)d_in[6];
    const float* bih2 = (const float*)d_in[7];
    const float* bhh2 = (const float*)d_in[8];
    const float* Wih3 = (const float*)d_in[9];
    const float* Whh3 = (const float*)d_in[10];
    const float* bih3 = (const float*)d_in[11];
    const float* bhh3 = (const float*)d_in[12];
    const float* Wd   = (const float*)d_in[13];
    const float* bd   = (const float*)d_in[14];
    const float* Ww   = (const float*)d_in[15];
    const float* bw   = (const float*)d_in[16];
    const float* Wo   = (const float*)d_in[17];
    const float* bo   = (const float*)d_in[18];
    float* out = (float*)d_out;

    float *xg1, *h3;
    __nv_bfloat16 *xbf, *W1bf;
    unsigned* xgcnt;
    cudaGetSymbolAddress((void**)&xg1,   g_xg1);
    cudaGetSymbolAddress((void**)&h3,    g_h3);
    cudaGetSymbolAddress((void**)&xbf,   g_xbf);
    cudaGetSymbolAddress((void**)&W1bf,  g_W1bf);
    cudaGetSymbolAddress((void**)&xgcnt, g_xgcnt);

    prep_zero<<<120, 512>>>();

    // convert x and Wih1 to bf16 for the big GEMM
    f2bf_kernel<<<4096, 256>>>(x,    xbf,  (BB * TT * DD) / 4);
    f2bf_kernel<<<512,  256>>>(Wih1, W1bf, (4 * H1 * DD) / 4);

    // mega kernel: gemm (producer, t-chunk-ordered) + 2 batch-group recurrences
    {
        const int dynBytes = 4 * (128 + 128) * 40 * 2;   // 81920 (gemm; lstm max ~34.8KB)
        cudaFuncSetAttribute(mega, cudaFuncAttributeMaxDynamicSharedMemorySize, dynBytes);
        mega<<<NCTA_LSTM + NCTA_GEMM, 512, dynBytes>>>(
            xbf, W1bf, bih1, bhh1, xg1,
            Whh1, Wih2, Whh2, bih2, bhh2,
            Wih3, Whh3, bih3, bhh3,
            h3, xgcnt);
    }

    // head
    head_kernel<<<BB, 256>>>(x, h3, Wd, bd, Ww, bw, Wo, bo, out);

    (void)in_sizes; (void)n_in; (void)out_size;
}